// round 12
// baseline (speedup 1.0000x reference)
#include <cuda_runtime.h>
#include <math.h>

#define NB 32
#define NT 1024
#define ND 512
#define NN 16
#define NDEPTH 3
#define NCHUNK 64
#define TC (NT / NCHUNK)   // 16 timesteps per partial-sum chunk
#define TTO 16             // timesteps per output block

// Scratch (static device globals — no allocation)
__device__ float g_partial[NB * NCHUNK * ND];      // 4 MB partial sums
__device__ float g_A[NDEPTH * NB * ND];            // per-depth additive offset c_d[b,:]
__device__ float g_S[NDEPTH * NB * ND];            // per-depth scale sel_d[b,:]

// evict_last load of a float4 (keeps x biased to stay in L2 until out reads it)
__device__ __forceinline__ float4 ld_evict_last(const float4* p, unsigned long long pol) {
    float4 v;
    asm volatile("ld.global.L2::cache_hint.v4.f32 {%0,%1,%2,%3}, [%4], %5;"
                 : "=f"(v.x), "=f"(v.y), "=f"(v.z), "=f"(v.w)
                 : "l"(p), "l"(pol));
    return v;
}

// ---------------------------------------------------------------------------
// Kernel 1: partial sums of x over T with L2::evict_last reads.
// grid = NB*NCHUNK = 2048 blocks, 128 threads.
// ---------------------------------------------------------------------------
__global__ void __launch_bounds__(128) pool_kernel(const float* __restrict__ x) {
    unsigned long long pol;
    asm volatile("createpolicy.fractional.L2::evict_last.b64 %0, 1.0;" : "=l"(pol));

    int blk = blockIdx.x;               // b * NCHUNK + chunk
    int b = blk >> 6;                   // / NCHUNK
    int c = blk & (NCHUNK - 1);
    int g = threadIdx.x;                // 0..127 (float4 group over DIM)
    const float4* xp = (const float4*)(x) + ((size_t)b * NT + (size_t)c * TC) * (ND / 4) + g;

    float4 v[TC];
#pragma unroll
    for (int t = 0; t < TC; ++t)
        v[t] = ld_evict_last(xp + (size_t)t * (ND / 4), pol);

#pragma unroll
    for (int s = TC / 2; s > 0; s >>= 1)
#pragma unroll
        for (int t = 0; t < s; ++t) {
            v[t].x += v[t + s].x; v[t].y += v[t + s].y;
            v[t].z += v[t + s].z; v[t].w += v[t + s].w;
        }

    ((float4*)g_partial)[(size_t)blk * (ND / 4) + g] = v[0];
}

// ---------------------------------------------------------------------------
// Kernel 2: per-batch decision chain. grid = NB blocks, 512 threads (= DIM).
// argmax(log softmax(logits) + g) == argmax(logits + g): LSE is constant
// across n, so no exp/log needed. Warp-shuffle argmax in warp 0.
// ---------------------------------------------------------------------------
__global__ void decide_kernel(const float* __restrict__ kd0,
                              const float* __restrict__ kd1,
                              const float* __restrict__ kd2,
                              const float* __restrict__ vd0,
                              const float* __restrict__ vd1,
                              const float* __restrict__ vd2,
                              const float* __restrict__ W,
                              const float* __restrict__ gum) {
    int b = blockIdx.x;
    int i = threadIdx.x;                // 0..511 (dim)
    int lane = i & 31;
    int wid = i >> 5;                   // 0..15 (one warp per node n)

    __shared__ float sp[ND];
    __shared__ float slog[NN];
    __shared__ int   sik;

    // pooled_base[b,i] = mean_t x[b,t,i]  — batched loads (16 in flight)
    float pooled = 0.f;
#pragma unroll
    for (int c0 = 0; c0 < NCHUNK; c0 += 16) {
        float p[16];
#pragma unroll
        for (int j = 0; j < 16; ++j)
            p[j] = g_partial[(size_t)(b * NCHUNK + c0 + j) * ND + i];
#pragma unroll
        for (int j = 0; j < 16; ++j) pooled += p[j];
    }
    pooled *= (1.0f / NT);

    const float* kds[NDEPTH] = {kd0, kd1, kd2};
    const float* vds[NDEPTH] = {vd0, vd1, vd2};

    float cacc = 0.f;   // cumulative W-row offset for this dim
    int node = 0;
    int ik = 0;

    for (int d = 0; d < NDEPTH; ++d) {
        if (d > 0) cacc += W[(size_t)ik * ND + i];
        sp[i] = pooled + cacc;
        __syncthreads();

        // warp `wid` computes logits[wid] = dot(sp, keys[d][node, wid, :])
        const float* krow = kds[d] + ((size_t)node * NN + wid) * ND;
        float s = 0.f;
#pragma unroll
        for (int j = lane; j < ND; j += 32) s += sp[j] * krow[j];
#pragma unroll
        for (int o = 16; o; o >>= 1) s += __shfl_down_sync(0xffffffffu, s, o);
        if (lane == 0) slog[wid] = s;
        __syncthreads();

        // warp 0: argmax over (logits + gumbel), first-max wins (matches jnp.argmax)
        if (wid == 0) {
            float sc = (lane < NN)
                ? slog[lane] + gum[((size_t)d * NB + b) * NN + lane]
                : -INFINITY;
            int best = lane;
#pragma unroll
            for (int o = 8; o; o >>= 1) {
                float osc = __shfl_down_sync(0xffffffffu, sc, o);
                int obest = __shfl_down_sync(0xffffffffu, best, o);
                // strict > keeps the lower index on ties (first-max)
                if (osc > sc) { sc = osc; best = obest; }
            }
            if (lane == 0) sik = best;
        }
        __syncthreads();
        ik = sik;

        // store offset & scale for the output pass
        g_A[((size_t)d * NB + b) * ND + i] = cacc;
        g_S[((size_t)d * NB + b) * ND + i] = vds[d][((size_t)node * NN + ik) * ND + i];
        node = node * NN + ik;
    }
}

// ---------------------------------------------------------------------------
// Kernel 3: streaming output. Reads each x element ONCE (__ldcs), then emits
// stores GROUPED BY DEPTH REGION: all 8 stores to out[0], then out[1], then
// out[2]. Per block that's 32KB contiguous per region burst (vs interleaving
// 3 far-apart pages every iteration) — better DRAM page locality.
//   out[d,b,t,:] = (x[b,t,:] + A[d,b,:]) * S[d,b,:]
// grid = (NT/TTO, NB), blockDim = (128, 2).
// ---------------------------------------------------------------------------
__global__ void __launch_bounds__(256) out_kernel(const float* __restrict__ x,
                                                  float* __restrict__ out) {
    int b = blockIdx.y;
    int g = threadIdx.x;                // float4 dim group 0..127
    int t0 = blockIdx.x * TTO + threadIdx.y * (TTO / 2);   // 8 consecutive t's

    const float4* A4 = (const float4*)g_A;
    const float4* S4 = (const float4*)g_S;
    int off = b * (ND / 4) + g;
    float4 a0 = A4[0 * NB * (ND / 4) + off];
    float4 a1 = A4[1 * NB * (ND / 4) + off];
    float4 a2 = A4[2 * NB * (ND / 4) + off];
    float4 s0 = S4[0 * NB * (ND / 4) + off];
    float4 s1 = S4[1 * NB * (ND / 4) + off];
    float4 s2 = S4[2 * NB * (ND / 4) + off];

    const float4* xp = (const float4*)x;
    float4* op = (float4*)out;
    const size_t stride_d = (size_t)NB * NT * (ND / 4);
    const size_t base = ((size_t)b * NT + t0) * (ND / 4) + g;

    float4 v[8];
#pragma unroll
    for (int i = 0; i < 8; ++i)
        v[i] = __ldcs(&xp[base + (size_t)i * (ND / 4)]);

    // depth 0 burst
#pragma unroll
    for (int i = 0; i < 8; ++i) {
        float4 r;
        r.x = (v[i].x + a0.x) * s0.x; r.y = (v[i].y + a0.y) * s0.y;
        r.z = (v[i].z + a0.z) * s0.z; r.w = (v[i].w + a0.w) * s0.w;
        __stcs(&op[base + (size_t)i * (ND / 4)], r);
    }
    // depth 1 burst
#pragma unroll
    for (int i = 0; i < 8; ++i) {
        float4 r;
        r.x = (v[i].x + a1.x) * s1.x; r.y = (v[i].y + a1.y) * s1.y;
        r.z = (v[i].z + a1.z) * s1.z; r.w = (v[i].w + a1.w) * s1.w;
        __stcs(&op[base + stride_d + (size_t)i * (ND / 4)], r);
    }
    // depth 2 burst
#pragma unroll
    for (int i = 0; i < 8; ++i) {
        float4 r;
        r.x = (v[i].x + a2.x) * s2.x; r.y = (v[i].y + a2.y) * s2.y;
        r.z = (v[i].z + a2.z) * s2.z; r.w = (v[i].w + a2.w) * s2.w;
        __stcs(&op[base + 2 * stride_d + (size_t)i * (ND / 4)], r);
    }
}

// ---------------------------------------------------------------------------
extern "C" void kernel_launch(void* const* d_in, const int* in_sizes, int n_in,
                              void* d_out, int out_size) {
    const float* x   = (const float*)d_in[0];
    const float* kd0 = (const float*)d_in[1];
    const float* kd1 = (const float*)d_in[2];
    const float* kd2 = (const float*)d_in[3];
    const float* vd0 = (const float*)d_in[4];
    const float* vd1 = (const float*)d_in[5];
    const float* vd2 = (const float*)d_in[6];
    const float* W   = (const float*)d_in[7];
    const float* gum = (const float*)d_in[8];
    float* out = (float*)d_out;

    pool_kernel<<<NB * NCHUNK, 128>>>(x);
    decide_kernel<<<NB, ND>>>(kd0, kd1, kd2, vd0, vd1, vd2, W, gum);
    out_kernel<<<dim3(NT / TTO, NB), dim3(128, 2)>>>(x, out);
}

// round 13
// speedup vs baseline: 1.0262x; 1.0262x over previous
#include <cuda_runtime.h>
#include <math.h>

#define NB 32
#define NT 1024
#define ND 512
#define NN 16
#define NDEPTH 3
#define NCHUNK 64
#define TC (NT / NCHUNK)   // 16 timesteps per partial-sum chunk
#define TTO 8              // timesteps per output block (threadIdx.y pair: 4 each)

// Scratch (static device globals — no allocation)
__device__ float g_partial[NB * NCHUNK * ND];      // 4 MB partial sums
__device__ float g_A[NDEPTH * NB * ND];            // per-depth additive offset c_d[b,:]
__device__ float g_S[NDEPTH * NB * ND];            // per-depth scale sel_d[b,:]

// evict_last load of a float4 (keeps x biased to stay in L2 until out reads it)
__device__ __forceinline__ float4 ld_evict_last(const float4* p, unsigned long long pol) {
    float4 v;
    asm volatile("ld.global.L2::cache_hint.v4.f32 {%0,%1,%2,%3}, [%4], %5;"
                 : "=f"(v.x), "=f"(v.y), "=f"(v.z), "=f"(v.w)
                 : "l"(p), "l"(pol));
    return v;
}

// ---------------------------------------------------------------------------
// Kernel 1: partial sums of x over T with L2::evict_last reads.
// grid = NB*NCHUNK = 2048 blocks, 128 threads.
// ---------------------------------------------------------------------------
__global__ void __launch_bounds__(128) pool_kernel(const float* __restrict__ x) {
    unsigned long long pol;
    asm volatile("createpolicy.fractional.L2::evict_last.b64 %0, 1.0;" : "=l"(pol));

    int blk = blockIdx.x;               // b * NCHUNK + chunk
    int b = blk >> 6;                   // / NCHUNK
    int c = blk & (NCHUNK - 1);
    int g = threadIdx.x;                // 0..127 (float4 group over DIM)
    const float4* xp = (const float4*)(x) + ((size_t)b * NT + (size_t)c * TC) * (ND / 4) + g;

    float4 v[TC];
#pragma unroll
    for (int t = 0; t < TC; ++t)
        v[t] = ld_evict_last(xp + (size_t)t * (ND / 4), pol);

#pragma unroll
    for (int s = TC / 2; s > 0; s >>= 1)
#pragma unroll
        for (int t = 0; t < s; ++t) {
            v[t].x += v[t + s].x; v[t].y += v[t + s].y;
            v[t].z += v[t + s].z; v[t].w += v[t + s].w;
        }

    ((float4*)g_partial)[(size_t)blk * (ND / 4) + g] = v[0];
}

// ---------------------------------------------------------------------------
// Kernel 2: per-batch decision chain. grid = NB blocks, 512 threads (= DIM).
// argmax(log softmax(logits) + g) == argmax(logits + g): LSE is constant
// across n, so no exp/log needed. Warp-shuffle argmax in warp 0.
// ---------------------------------------------------------------------------
__global__ void decide_kernel(const float* __restrict__ kd0,
                              const float* __restrict__ kd1,
                              const float* __restrict__ kd2,
                              const float* __restrict__ vd0,
                              const float* __restrict__ vd1,
                              const float* __restrict__ vd2,
                              const float* __restrict__ W,
                              const float* __restrict__ gum) {
    int b = blockIdx.x;
    int i = threadIdx.x;                // 0..511 (dim)
    int lane = i & 31;
    int wid = i >> 5;                   // 0..15 (one warp per node n)

    __shared__ float sp[ND];
    __shared__ float slog[NN];
    __shared__ int   sik;

    // pooled_base[b,i] = mean_t x[b,t,i]  — batched loads (16 in flight)
    float pooled = 0.f;
#pragma unroll
    for (int c0 = 0; c0 < NCHUNK; c0 += 16) {
        float p[16];
#pragma unroll
        for (int j = 0; j < 16; ++j)
            p[j] = g_partial[(size_t)(b * NCHUNK + c0 + j) * ND + i];
#pragma unroll
        for (int j = 0; j < 16; ++j) pooled += p[j];
    }
    pooled *= (1.0f / NT);

    const float* kds[NDEPTH] = {kd0, kd1, kd2};
    const float* vds[NDEPTH] = {vd0, vd1, vd2};

    float cacc = 0.f;   // cumulative W-row offset for this dim
    int node = 0;
    int ik = 0;

    for (int d = 0; d < NDEPTH; ++d) {
        if (d > 0) cacc += W[(size_t)ik * ND + i];
        sp[i] = pooled + cacc;
        __syncthreads();

        // warp `wid` computes logits[wid] = dot(sp, keys[d][node, wid, :])
        const float* krow = kds[d] + ((size_t)node * NN + wid) * ND;
        float s = 0.f;
#pragma unroll
        for (int j = lane; j < ND; j += 32) s += sp[j] * krow[j];
#pragma unroll
        for (int o = 16; o; o >>= 1) s += __shfl_down_sync(0xffffffffu, s, o);
        if (lane == 0) slog[wid] = s;
        __syncthreads();

        // warp 0: argmax over (logits + gumbel), first-max wins (matches jnp.argmax)
        if (wid == 0) {
            float sc = (lane < NN)
                ? slog[lane] + gum[((size_t)d * NB + b) * NN + lane]
                : -INFINITY;
            int best = lane;
#pragma unroll
            for (int o = 8; o; o >>= 1) {
                float osc = __shfl_down_sync(0xffffffffu, sc, o);
                int obest = __shfl_down_sync(0xffffffffu, best, o);
                // strict > keeps the lower index on ties (first-max)
                if (osc > sc) { sc = osc; best = obest; }
            }
            if (lane == 0) sik = best;
        }
        __syncthreads();
        ik = sik;

        // store offset & scale for the output pass
        g_A[((size_t)d * NB + b) * ND + i] = cacc;
        g_S[((size_t)d * NB + b) * ND + i] = vds[d][((size_t)node * NN + ik) * ND + i];
        node = node * NN + ik;
    }
}

// ---------------------------------------------------------------------------
// Kernel 3: streaming output (R11-best interleaved store pattern, smaller
// per-thread tile). Reads each x element ONCE (__ldcs), writes all 3 depths
// interleaved (spreads stores across LTS partitions/DRAM channels):
//   out[d,b,t,:] = (x[b,t,:] + A[d,b,:]) * S[d,b,:]
// grid = (NT/TTO = 128, NB), blockDim = (128, 2); 4 t's per thread.
// ---------------------------------------------------------------------------
__global__ void __launch_bounds__(256) out_kernel(const float* __restrict__ x,
                                                  float* __restrict__ out) {
    int b = blockIdx.y;
    int g = threadIdx.x;                // float4 dim group 0..127
    int t0 = blockIdx.x * TTO + threadIdx.y * (TTO / 2);   // 4 consecutive t's

    const float4* A4 = (const float4*)g_A;
    const float4* S4 = (const float4*)g_S;
    int off = b * (ND / 4) + g;
    float4 a0 = A4[0 * NB * (ND / 4) + off];
    float4 a1 = A4[1 * NB * (ND / 4) + off];
    float4 a2 = A4[2 * NB * (ND / 4) + off];
    float4 s0 = S4[0 * NB * (ND / 4) + off];
    float4 s1 = S4[1 * NB * (ND / 4) + off];
    float4 s2 = S4[2 * NB * (ND / 4) + off];

    const float4* xp = (const float4*)x;
    float4* op = (float4*)out;
    const size_t stride_d = (size_t)NB * NT * (ND / 4);
    const size_t base = ((size_t)b * NT + t0) * (ND / 4) + g;

    float4 v[TTO / 2];
#pragma unroll
    for (int i = 0; i < TTO / 2; ++i)
        v[i] = __ldcs(&xp[base + (size_t)i * (ND / 4)]);

#pragma unroll
    for (int i = 0; i < TTO / 2; ++i) {
        size_t idx = base + (size_t)i * (ND / 4);
        float4 r0, r1, r2;
        r0.x = (v[i].x + a0.x) * s0.x; r0.y = (v[i].y + a0.y) * s0.y;
        r0.z = (v[i].z + a0.z) * s0.z; r0.w = (v[i].w + a0.w) * s0.w;
        r1.x = (v[i].x + a1.x) * s1.x; r1.y = (v[i].y + a1.y) * s1.y;
        r1.z = (v[i].z + a1.z) * s1.z; r1.w = (v[i].w + a1.w) * s1.w;
        r2.x = (v[i].x + a2.x) * s2.x; r2.y = (v[i].y + a2.y) * s2.y;
        r2.z = (v[i].z + a2.z) * s2.z; r2.w = (v[i].w + a2.w) * s2.w;
        __stcs(&op[idx], r0);
        __stcs(&op[idx + stride_d], r1);
        __stcs(&op[idx + 2 * stride_d], r2);
    }
}

// ---------------------------------------------------------------------------
extern "C" void kernel_launch(void* const* d_in, const int* in_sizes, int n_in,
                              void* d_out, int out_size) {
    const float* x   = (const float*)d_in[0];
    const float* kd0 = (const float*)d_in[1];
    const float* kd1 = (const float*)d_in[2];
    const float* kd2 = (const float*)d_in[3];
    const float* vd0 = (const float*)d_in[4];
    const float* vd1 = (const float*)d_in[5];
    const float* vd2 = (const float*)d_in[6];
    const float* W   = (const float*)d_in[7];
    const float* gum = (const float*)d_in[8];
    float* out = (float*)d_out;

    pool_kernel<<<NB * NCHUNK, 128>>>(x);
    decide_kernel<<<NB, ND>>>(kd0, kd1, kd2, vd0, vd1, vd2, W, gum);
    out_kernel<<<dim3(NT / TTO, NB), dim3(128, 2)>>>(x, out);
}

// round 14
// speedup vs baseline: 1.0278x; 1.0016x over previous
#include <cuda_runtime.h>
#include <math.h>

#define NB 32
#define NT 1024
#define ND 512
#define NN 16
#define NDEPTH 3
#define NCHUNK 64
#define TC (NT / NCHUNK)   // 16 timesteps per partial-sum chunk
#define TTO 8              // timesteps per output block (threadIdx.y pair: 4 each)

// Scratch (static device globals — no allocation)
__device__ float g_partial[NB * NCHUNK * ND];      // 4 MB partial sums
__device__ float g_A[NDEPTH * NB * ND];            // per-depth additive offset c_d[b,:]
__device__ float g_S[NDEPTH * NB * ND];            // per-depth scale sel_d[b,:]

// evict_last load of a float4 (keeps x biased to stay in L2 until out reads it)
__device__ __forceinline__ float4 ld_evict_last(const float4* p, unsigned long long pol) {
    float4 v;
    asm volatile("ld.global.L2::cache_hint.v4.f32 {%0,%1,%2,%3}, [%4], %5;"
                 : "=f"(v.x), "=f"(v.y), "=f"(v.z), "=f"(v.w)
                 : "l"(p), "l"(pol));
    return v;
}

// ---------------------------------------------------------------------------
// Kernel 1: partial sums of x over T with L2::evict_last reads.
// grid = NB*NCHUNK = 2048 blocks, 128 threads. Streams x front-to-back.
// ---------------------------------------------------------------------------
__global__ void __launch_bounds__(128) pool_kernel(const float* __restrict__ x) {
    unsigned long long pol;
    asm volatile("createpolicy.fractional.L2::evict_last.b64 %0, 1.0;" : "=l"(pol));

    int blk = blockIdx.x;               // b * NCHUNK + chunk
    int b = blk >> 6;                   // / NCHUNK
    int c = blk & (NCHUNK - 1);
    int g = threadIdx.x;                // 0..127 (float4 group over DIM)
    const float4* xp = (const float4*)(x) + ((size_t)b * NT + (size_t)c * TC) * (ND / 4) + g;

    float4 v[TC];
#pragma unroll
    for (int t = 0; t < TC; ++t)
        v[t] = ld_evict_last(xp + (size_t)t * (ND / 4), pol);

#pragma unroll
    for (int s = TC / 2; s > 0; s >>= 1)
#pragma unroll
        for (int t = 0; t < s; ++t) {
            v[t].x += v[t + s].x; v[t].y += v[t + s].y;
            v[t].z += v[t + s].z; v[t].w += v[t + s].w;
        }

    ((float4*)g_partial)[(size_t)blk * (ND / 4) + g] = v[0];
}

// ---------------------------------------------------------------------------
// Kernel 2: per-batch decision chain. grid = NB blocks, 512 threads (= DIM).
// argmax(log softmax(logits) + g) == argmax(logits + g): LSE is constant
// across n, so no exp/log needed. Warp-shuffle argmax in warp 0.
// ---------------------------------------------------------------------------
__global__ void decide_kernel(const float* __restrict__ kd0,
                              const float* __restrict__ kd1,
                              const float* __restrict__ kd2,
                              const float* __restrict__ vd0,
                              const float* __restrict__ vd1,
                              const float* __restrict__ vd2,
                              const float* __restrict__ W,
                              const float* __restrict__ gum) {
    int b = blockIdx.x;
    int i = threadIdx.x;                // 0..511 (dim)
    int lane = i & 31;
    int wid = i >> 5;                   // 0..15 (one warp per node n)

    __shared__ float sp[ND];
    __shared__ float slog[NN];
    __shared__ int   sik;

    // pooled_base[b,i] = mean_t x[b,t,i]  — batched loads (16 in flight)
    float pooled = 0.f;
#pragma unroll
    for (int c0 = 0; c0 < NCHUNK; c0 += 16) {
        float p[16];
#pragma unroll
        for (int j = 0; j < 16; ++j)
            p[j] = g_partial[(size_t)(b * NCHUNK + c0 + j) * ND + i];
#pragma unroll
        for (int j = 0; j < 16; ++j) pooled += p[j];
    }
    pooled *= (1.0f / NT);

    const float* kds[NDEPTH] = {kd0, kd1, kd2};
    const float* vds[NDEPTH] = {vd0, vd1, vd2};

    float cacc = 0.f;   // cumulative W-row offset for this dim
    int node = 0;
    int ik = 0;

    for (int d = 0; d < NDEPTH; ++d) {
        if (d > 0) cacc += W[(size_t)ik * ND + i];
        sp[i] = pooled + cacc;
        __syncthreads();

        // warp `wid` computes logits[wid] = dot(sp, keys[d][node, wid, :])
        const float* krow = kds[d] + ((size_t)node * NN + wid) * ND;
        float s = 0.f;
#pragma unroll
        for (int j = lane; j < ND; j += 32) s += sp[j] * krow[j];
#pragma unroll
        for (int o = 16; o; o >>= 1) s += __shfl_down_sync(0xffffffffu, s, o);
        if (lane == 0) slog[wid] = s;
        __syncthreads();

        // warp 0: argmax over (logits + gumbel), first-max wins (matches jnp.argmax)
        if (wid == 0) {
            float sc = (lane < NN)
                ? slog[lane] + gum[((size_t)d * NB + b) * NN + lane]
                : -INFINITY;
            int best = lane;
#pragma unroll
            for (int o = 8; o; o >>= 1) {
                float osc = __shfl_down_sync(0xffffffffu, sc, o);
                int obest = __shfl_down_sync(0xffffffffu, best, o);
                // strict > keeps the lower index on ties (first-max)
                if (osc > sc) { sc = osc; best = obest; }
            }
            if (lane == 0) sik = best;
        }
        __syncthreads();
        ik = sik;

        // store offset & scale for the output pass
        g_A[((size_t)d * NB + b) * ND + i] = cacc;
        g_S[((size_t)d * NB + b) * ND + i] = vds[d][((size_t)node * NN + ik) * ND + i];
        node = node * NN + ik;
    }
}

// ---------------------------------------------------------------------------
// Kernel 3: streaming output, REVERSE-ORDER over x for L2 LIFO reuse:
// the earliest out blocks read the x region pool touched LAST (still L2-
// resident), so reads hit L2 instead of chasing already-evicted lines.
//   out[d,b,t,:] = (x[b,t,:] + A[d,b,:]) * S[d,b,:]
// grid = (NT/TTO = 128, NB), blockDim = (128, 2); 4 t's per thread;
// interleaved evict-first stores (best measured pattern).
// ---------------------------------------------------------------------------
__global__ void __launch_bounds__(256) out_kernel(const float* __restrict__ x,
                                                  float* __restrict__ out) {
    int b  = NB - 1 - blockIdx.y;                       // reversed batch
    int tb = (NT / TTO) - 1 - blockIdx.x;               // reversed t-block
    int g = threadIdx.x;                                // float4 dim group 0..127
    int t0 = tb * TTO + threadIdx.y * (TTO / 2);        // 4 consecutive t's

    const float4* A4 = (const float4*)g_A;
    const float4* S4 = (const float4*)g_S;
    int off = b * (ND / 4) + g;
    float4 a0 = A4[0 * NB * (ND / 4) + off];
    float4 a1 = A4[1 * NB * (ND / 4) + off];
    float4 a2 = A4[2 * NB * (ND / 4) + off];
    float4 s0 = S4[0 * NB * (ND / 4) + off];
    float4 s1 = S4[1 * NB * (ND / 4) + off];
    float4 s2 = S4[2 * NB * (ND / 4) + off];

    const float4* xp = (const float4*)x;
    float4* op = (float4*)out;
    const size_t stride_d = (size_t)NB * NT * (ND / 4);
    const size_t base = ((size_t)b * NT + t0) * (ND / 4) + g;

    float4 v[TTO / 2];
#pragma unroll
    for (int i = 0; i < TTO / 2; ++i)
        v[i] = __ldcs(&xp[base + (size_t)i * (ND / 4)]);

#pragma unroll
    for (int i = 0; i < TTO / 2; ++i) {
        size_t idx = base + (size_t)i * (ND / 4);
        float4 r0, r1, r2;
        r0.x = (v[i].x + a0.x) * s0.x; r0.y = (v[i].y + a0.y) * s0.y;
        r0.z = (v[i].z + a0.z) * s0.z; r0.w = (v[i].w + a0.w) * s0.w;
        r1.x = (v[i].x + a1.x) * s1.x; r1.y = (v[i].y + a1.y) * s1.y;
        r1.z = (v[i].z + a1.z) * s1.z; r1.w = (v[i].w + a1.w) * s1.w;
        r2.x = (v[i].x + a2.x) * s2.x; r2.y = (v[i].y + a2.y) * s2.y;
        r2.z = (v[i].z + a2.z) * s2.z; r2.w = (v[i].w + a2.w) * s2.w;
        __stcs(&op[idx], r0);
        __stcs(&op[idx + stride_d], r1);
        __stcs(&op[idx + 2 * stride_d], r2);
    }
}

// ---------------------------------------------------------------------------
extern "C" void kernel_launch(void* const* d_in, const int* in_sizes, int n_in,
                              void* d_out, int out_size) {
    const float* x   = (const float*)d_in[0];
    const float* kd0 = (const float*)d_in[1];
    const float* kd1 = (const float*)d_in[2];
    const float* kd2 = (const float*)d_in[3];
    const float* vd0 = (const float*)d_in[4];
    const float* vd1 = (const float*)d_in[5];
    const float* vd2 = (const float*)d_in[6];
    const float* W   = (const float*)d_in[7];
    const float* gum = (const float*)d_in[8];
    float* out = (float*)d_out;

    pool_kernel<<<NB * NCHUNK, 128>>>(x);
    decide_kernel<<<NB, ND>>>(kd0, kd1, kd2, vd0, vd1, vd2, W, gum);
    out_kernel<<<dim3(NT / TTO, NB), dim3(128, 2)>>>(x, out);
}